// round 10
// baseline (speedup 1.0000x reference)
#include <cuda_runtime.h>
#include <cuda_bf16.h>

#define NTOK 50
#define BTOK 3200
#define P    72                 // plane pitch in bf16 elems (144B rows; LDSM conflict-free)
#define PB   (P*2)              // 144 B
#define PLANE_E (64*P)
#define PLANE_B (64*PB)         // 9216 B

// plane indices (each PLANE_B bytes):
// 0 FhA  1 FlA  2 FhB  3 FlB  4 Kh(->GhA)  5 Kl(->GlA)  6 Qh(->HhA)
// 7 GhB  8 GlB  9 HlA  10 HhB  11 HlB
#define NPLANES 12
#define SMEM_BYTES (NPLANES*PLANE_B)   // 110,592 B -> 2 CTAs/SM

__device__ __forceinline__ void ldsm_x4(unsigned* r, unsigned a) {
    asm volatile("ldmatrix.sync.aligned.m8n8.x4.shared.b16 {%0,%1,%2,%3}, [%4];"
                 : "=r"(r[0]), "=r"(r[1]), "=r"(r[2]), "=r"(r[3]) : "r"(a));
}
__device__ __forceinline__ void ldsm_x4t(unsigned* r, unsigned a) {
    asm volatile("ldmatrix.sync.aligned.m8n8.x4.trans.shared.b16 {%0,%1,%2,%3}, [%4];"
                 : "=r"(r[0]), "=r"(r[1]), "=r"(r[2]), "=r"(r[3]) : "r"(a));
}
__device__ __forceinline__ void mma16(float* d, const unsigned* a, const unsigned* b) {
    asm volatile(
        "mma.sync.aligned.m16n8k16.row.col.f32.bf16.bf16.f32 "
        "{%0,%1,%2,%3}, {%4,%5,%6,%7}, {%8,%9}, {%0,%1,%2,%3};\n"
        : "+f"(d[0]), "+f"(d[1]), "+f"(d[2]), "+f"(d[3])
        : "r"(a[0]), "r"(a[1]), "r"(a[2]), "r"(a[3]), "r"(b[0]), "r"(b[1]));
}
__device__ __forceinline__ void bsplit(float x, __nv_bfloat16& h, __nv_bfloat16& l) {
    h = __float2bfloat16_rn(x);
    l = __float2bfloat16_rn(x - __bfloat162float(h));
}

__global__ __launch_bounds__(256, 2)
void SAM3E_kernel(const float* __restrict__ Fg,
                  const float* __restrict__ Kw,
                  const float* __restrict__ Qw,
                  float* __restrict__ outg)
{
    extern __shared__ __nv_bfloat16 sb[];
    const unsigned sbase = (unsigned)__cvta_generic_to_shared(sb);
    const int tid = threadIdx.x;
    const int b2  = blockIdx.x * 2;

    // ---- stage: split fp32 -> bf16 hi/lo planes (2 batches; K/Q shared) ----
    const float2* F0 = (const float2*)(Fg + (size_t)b2 * BTOK);
    const float2* F1 = (const float2*)(Fg + (size_t)(b2 + 1) * BTOK);
    for (int i = tid; i < 1600; i += 256) {
        int n = i >> 5, d = (i & 31) << 1;
        __nv_bfloat16 hx, lx, hy, ly;
        float2 v = F0[i];
        bsplit(v.x, hx, lx); bsplit(v.y, hy, ly);
        *(__nv_bfloat162*)&sb[0*PLANE_E + n*P + d] = __halves2bfloat162(hx, hy);
        *(__nv_bfloat162*)&sb[1*PLANE_E + n*P + d] = __halves2bfloat162(lx, ly);
        float2 u = F1[i];
        bsplit(u.x, hx, lx); bsplit(u.y, hy, ly);
        *(__nv_bfloat162*)&sb[2*PLANE_E + n*P + d] = __halves2bfloat162(hx, hy);
        *(__nv_bfloat162*)&sb[3*PLANE_E + n*P + d] = __halves2bfloat162(lx, ly);
    }
    for (int i = tid; i < 14 * (P / 2); i += 256) {     // zero-pad rows 50..63
        int off = 50 * P + 2 * i;
        *(unsigned*)&sb[0*PLANE_E + off] = 0u;
        *(unsigned*)&sb[1*PLANE_E + off] = 0u;
        *(unsigned*)&sb[2*PLANE_E + off] = 0u;
        *(unsigned*)&sb[3*PLANE_E + off] = 0u;
    }
    const float2* K2 = (const float2*)Kw;
    const float2* Q2 = (const float2*)Qw;
    for (int i = tid; i < 2048; i += 256) {
        int r = i >> 5, c = (i & 31) << 1;
        __nv_bfloat16 hx, lx, hy, ly;
        float2 v = K2[i];
        bsplit(v.x, hx, lx); bsplit(v.y, hy, ly);
        *(__nv_bfloat162*)&sb[4*PLANE_E + r*P + c] = __halves2bfloat162(hx, hy);
        *(__nv_bfloat162*)&sb[5*PLANE_E + r*P + c] = __halves2bfloat162(lx, ly);
        float2 u = Q2[i];                               // Q: hi-only (1-term branch)
        *(__nv_bfloat162*)&sb[6*PLANE_E + r*P + c] =
            __halves2bfloat162(__float2bfloat16_rn(u.x), __float2bfloat16_rn(u.y));
    }
    __syncthreads();

    const int lane = tid & 31, w = tid >> 5;
    const int bi = w >> 2;                  // batch within CTA
    const int wb = w & 3;
    const int m0 = (wb & 1) * 32;           // 32-row band
    const int n0 = (wb >> 1) * 32;          // 32-col band (4 n8-tiles)
    const int q   = lane & 7;
    const int b8  = (lane >> 3) & 1;
    const int b16 = (lane >> 4) & 1;
    const int g   = lane >> 2, t4 = lane & 3;

    const unsigned fb = sbase + (unsigned)(2 * bi) * PLANE_B;     // Fh plane (Fl = +PLANE_B)

    // ========== Phase A2: H = F @ K_w (3-term), QF = F @ Q_w^T (1-term) ==========
    float accH[8][4] = {};      // [m16-half*4 + n8-tile]
    float accQ[8][4] = {};
    {
        const unsigned aB = fb + 2u * ((m0 + 8 * b8 + q) * P + 8 * b16);
        const unsigned bk = sbase + 4u * PLANE_B + 2u * ((8 * b8 + q) * P + n0 + 8 * b16);
        const unsigned bq = sbase + 6u * PLANE_B + 2u * ((n0 + q + 8 * b16) * P + 8 * b8);
        #pragma unroll
        for (int kk = 0; kk < 4; ++kk) {
            unsigned ah[2][4], al[2][4];
            ldsm_x4(ah[0], aB + kk * 32);
            ldsm_x4(al[0], aB + kk * 32 + PLANE_B);
            ldsm_x4(ah[1], aB + 16 * PB + kk * 32);
            ldsm_x4(al[1], aB + 16 * PB + kk * 32 + PLANE_B);
            #pragma unroll
            for (int p = 0; p < 2; ++p) {
                unsigned bh[4], bl[4], bq4[4];
                ldsm_x4t(bh, bk + kk * 16 * PB + p * 32);
                ldsm_x4t(bl, bk + kk * 16 * PB + p * 32 + PLANE_B);
                ldsm_x4 (bq4, bq + kk * 32 + p * 16 * PB);
                #pragma unroll
                for (int h2 = 0; h2 < 2; ++h2) {
                    float* H0 = accH[h2 * 4 + 2 * p];
                    float* H1 = accH[h2 * 4 + 2 * p + 1];
                    mma16(H0, ah[h2], bh);  mma16(H0, al[h2], bh);  mma16(H0, ah[h2], bl);
                    mma16(H1, ah[h2], bh+2); mma16(H1, al[h2], bh+2); mma16(H1, ah[h2], bl+2);
                    mma16(accQ[h2 * 4 + 2 * p    ], ah[h2], bq4);
                    mma16(accQ[h2 * 4 + 2 * p + 1], ah[h2], bq4 + 2);
                }
            }
        }
    }
    __syncthreads();   // all warps done reading K/Q -> those planes reusable

    // ---- store H (split) into planes: A->(6,9), B->(10,11) ----
    {
        __nv_bfloat16* sHh = sb + (bi ? 10 : 6) * PLANE_E;
        __nv_bfloat16* sHl = sb + (bi ? 11 : 9) * PLANE_E;
        #pragma unroll
        for (int h2 = 0; h2 < 2; ++h2) {
            const int r = m0 + 16 * h2 + g;
            #pragma unroll
            for (int t = 0; t < 4; ++t) {
                const int col = n0 + 8 * t + 2 * t4;
                const float* a = accH[h2 * 4 + t];
                __nv_bfloat16 h0,l0,h1,l1,h2b,l2,h3,l3;
                bsplit(a[0],h0,l0); bsplit(a[1],h1,l1); bsplit(a[2],h2b,l2); bsplit(a[3],h3,l3);
                *(__nv_bfloat162*)&sHh[(r    ) * P + col] = __halves2bfloat162(h0, h1);
                *(__nv_bfloat162*)&sHl[(r    ) * P + col] = __halves2bfloat162(l0, l1);
                *(__nv_bfloat162*)&sHh[(r + 8) * P + col] = __halves2bfloat162(h2b, h3);
                *(__nv_bfloat162*)&sHl[(r + 8) * P + col] = __halves2bfloat162(l2, l3);
            }
        }
    }

    // ========== Phase A1: G = F^T F (reads F only) -> planes A:(4,5) B:(7,8) ==========
    {
        float accG[8][4] = {};
        const unsigned a1 = fb + 2u * ((8 * b16 + q) * P + m0 + 8 * b8);
        const unsigned b1 = fb + 2u * ((8 * b8 + q) * P + n0 + 8 * b16);
        #pragma unroll
        for (int kk = 0; kk < 4; ++kk) {
            unsigned ah[2][4], al[2][4];
            ldsm_x4t(ah[0], a1 + kk * 16 * PB);
            ldsm_x4t(al[0], a1 + kk * 16 * PB + PLANE_B);
            ldsm_x4t(ah[1], a1 + 32 + kk * 16 * PB);           // second m16 band: +16 cols
            ldsm_x4t(al[1], a1 + 32 + kk * 16 * PB + PLANE_B);
            #pragma unroll
            for (int p = 0; p < 2; ++p) {
                unsigned bh[4], bl[4];
                ldsm_x4t(bh, b1 + kk * 16 * PB + p * 32);
                ldsm_x4t(bl, b1 + kk * 16 * PB + p * 32 + PLANE_B);
                #pragma unroll
                for (int h2 = 0; h2 < 2; ++h2) {
                    float* G0 = accG[h2 * 4 + 2 * p];
                    float* G1 = accG[h2 * 4 + 2 * p + 1];
                    mma16(G0, ah[h2], bh);  mma16(G0, al[h2], bh);  mma16(G0, ah[h2], bl);
                    mma16(G1, ah[h2], bh+2); mma16(G1, al[h2], bh+2); mma16(G1, ah[h2], bl+2);
                }
            }
        }
        __nv_bfloat16* sGh = sb + (bi ? 7 : 4) * PLANE_E;
        __nv_bfloat16* sGl = sb + (bi ? 8 : 5) * PLANE_E;
        #pragma unroll
        for (int h2 = 0; h2 < 2; ++h2) {
            const int r = m0 + 16 * h2 + g;
            #pragma unroll
            for (int t = 0; t < 4; ++t) {
                const int col = n0 + 8 * t + 2 * t4;
                const float* a = accG[h2 * 4 + t];
                __nv_bfloat16 h0,l0,h1,l1,h2b,l2,h3,l3;
                bsplit(a[0],h0,l0); bsplit(a[1],h1,l1); bsplit(a[2],h2b,l2); bsplit(a[3],h3,l3);
                *(__nv_bfloat162*)&sGh[(r    ) * P + col] = __halves2bfloat162(h0, h1);
                *(__nv_bfloat162*)&sGl[(r    ) * P + col] = __halves2bfloat162(l0, l1);
                *(__nv_bfloat162*)&sGh[(r + 8) * P + col] = __halves2bfloat162(h2b, h3);
                *(__nv_bfloat162*)&sGl[(r + 8) * P + col] = __halves2bfloat162(l2, l3);
            }
        }
    }
    __syncthreads();   // G + H visible

    // ========== Phase B: T = H @ G  (B = G rows via symmetry, non-trans) ==========
    float accT[8][4] = {};
    {
        const unsigned a3 = sbase + (bi ? 10u : 6u) * PLANE_B
                          + 2u * ((m0 + 8 * b8 + q) * P + 8 * b16);
        const unsigned hlo = (bi ? 1u : 3u) * PLANE_B;         // Hl plane offset from Hh
        const unsigned b3 = sbase + (bi ? 7u : 4u) * PLANE_B
                          + 2u * ((n0 + q + 8 * b16) * P + 8 * b8);
        #pragma unroll
        for (int kk = 0; kk < 4; ++kk) {
            unsigned ah[2][4], al[2][4];
            ldsm_x4(ah[0], a3 + kk * 32);
            ldsm_x4(al[0], a3 + kk * 32 + hlo);
            ldsm_x4(ah[1], a3 + 16 * PB + kk * 32);
            ldsm_x4(al[1], a3 + 16 * PB + kk * 32 + hlo);
            #pragma unroll
            for (int p = 0; p < 2; ++p) {
                unsigned bh[4], bl[4];
                ldsm_x4(bh, b3 + kk * 32 + p * 16 * PB);
                ldsm_x4(bl, b3 + kk * 32 + p * 16 * PB + PLANE_B);
                #pragma unroll
                for (int h2 = 0; h2 < 2; ++h2) {
                    float* T0 = accT[h2 * 4 + 2 * p];
                    float* T1 = accT[h2 * 4 + 2 * p + 1];
                    mma16(T0, ah[h2], bh);  mma16(T0, al[h2], bh);  mma16(T0, ah[h2], bl);
                    mma16(T1, ah[h2], bh+2); mma16(T1, al[h2], bh+2); mma16(T1, ah[h2], bl+2);
                }
            }
        }
    }

    // ========== Epilogue: out = F .* T + QF  (rows < 50) ==========
    float* ob = outg + (size_t)(b2 + bi) * BTOK;
    const __nv_bfloat16* sFh = sb + (2 * bi) * PLANE_E;
    const __nv_bfloat16* sFl = sFh + PLANE_E;
    #pragma unroll
    for (int h2 = 0; h2 < 2; ++h2) {
        const int r1 = m0 + 16 * h2 + g;
        const int r2 = r1 + 8;
        #pragma unroll
        for (int t = 0; t < 4; ++t) {
            const int col = n0 + 8 * t + 2 * t4;
            const float* tT = accT[h2 * 4 + t];
            const float* tQ = accQ[h2 * 4 + t];
            if (r1 < NTOK) {
                float2 fh = __bfloat1622float2(*(__nv_bfloat162*)&sFh[r1 * P + col]);
                float2 fl = __bfloat1622float2(*(__nv_bfloat162*)&sFl[r1 * P + col]);
                float2 o;
                o.x = (fh.x + fl.x) * tT[0] + tQ[0];
                o.y = (fh.y + fl.y) * tT[1] + tQ[1];
                *(float2*)&ob[r1 * 64 + col] = o;
            }
            if (r2 < NTOK) {
                float2 fh = __bfloat1622float2(*(__nv_bfloat162*)&sFh[r2 * P + col]);
                float2 fl = __bfloat1622float2(*(__nv_bfloat162*)&sFl[r2 * P + col]);
                float2 o;
                o.x = (fh.x + fl.x) * tT[2] + tQ[2];
                o.y = (fh.y + fl.y) * tT[3] + tQ[3];
                *(float2*)&ob[r2 * 64 + col] = o;
            }
        }
    }
}

extern "C" void kernel_launch(void* const* d_in, const int* in_sizes, int n_in,
                              void* d_out, int out_size)
{
    const float* F  = (const float*)d_in[0];
    const float* Kw = (const float*)d_in[1];
    const float* Qw = (const float*)d_in[2];
    float* out      = (float*)d_out;

    const int B = in_sizes[0] / BTOK;                   // 8192

    cudaFuncSetAttribute(SAM3E_kernel,
                         cudaFuncAttributeMaxDynamicSharedMemorySize, SMEM_BYTES);

    SAM3E_kernel<<<B / 2, 256, SMEM_BYTES>>>(F, Kw, Qw, out);
}

// round 11
// speedup vs baseline: 1.2120x; 1.2120x over previous
#include <cuda_runtime.h>
#include <cuda_bf16.h>

#define NTOK 50
#define BTOK 3200
#define P    72                 // plane pitch in bf16 elems (144B rows; LDSM conflict-free)
#define PB   (P*2)              // 144 B
#define PLANE_E (64*P)
#define PLANE_B (64*PB)         // 9216 B

// 6 planes: Fh Fl Kh Kl Qh X ; G aliases Kh/Kl, H aliases Qh/X (after barriers)
#define OFF_FH 0
#define OFF_FL (1*PLANE_B)
#define OFF_KH (2*PLANE_B)      // -> Gh
#define OFF_KL (3*PLANE_B)      // -> Gl
#define OFF_QH (4*PLANE_B)      // -> Hh
#define OFF_X  (5*PLANE_B)      // -> Hl
#define SMEM_BYTES (6*PLANE_B)  // 55,296 B -> 4 CTAs/SM

// pre-split weight planes (Kh, Kl, Qh) in pitch-P layout, ready for linear copy
__device__ __align__(16) __nv_bfloat16 gKQ[3 * PLANE_E];

__device__ __forceinline__ void ldsm_x4(unsigned* r, unsigned a) {
    asm volatile("ldmatrix.sync.aligned.m8n8.x4.shared.b16 {%0,%1,%2,%3}, [%4];"
                 : "=r"(r[0]), "=r"(r[1]), "=r"(r[2]), "=r"(r[3]) : "r"(a));
}
__device__ __forceinline__ void ldsm_x4t(unsigned* r, unsigned a) {
    asm volatile("ldmatrix.sync.aligned.m8n8.x4.trans.shared.b16 {%0,%1,%2,%3}, [%4];"
                 : "=r"(r[0]), "=r"(r[1]), "=r"(r[2]), "=r"(r[3]) : "r"(a));
}
__device__ __forceinline__ void mma16(float* d, const unsigned* a, const unsigned* b) {
    asm volatile(
        "mma.sync.aligned.m16n8k16.row.col.f32.bf16.bf16.f32 "
        "{%0,%1,%2,%3}, {%4,%5,%6,%7}, {%8,%9}, {%0,%1,%2,%3};\n"
        : "+f"(d[0]), "+f"(d[1]), "+f"(d[2]), "+f"(d[3])
        : "r"(a[0]), "r"(a[1]), "r"(a[2]), "r"(a[3]), "r"(b[0]), "r"(b[1]));
}
__device__ __forceinline__ void bsplit(float x, __nv_bfloat16& h, __nv_bfloat16& l) {
    h = __float2bfloat16_rn(x);
    l = __float2bfloat16_rn(x - __bfloat162float(h));
}

// ---- prep: split K_w/Q_w once per launch into gKQ planes ----
__global__ void SAM3E_prep(const float* __restrict__ Kw, const float* __restrict__ Qw)
{
    const int i = blockIdx.x * 256 + threadIdx.x;   // 0..2047, each handles 2 elems
    const int r = i >> 5, c = (i & 31) << 1;
    const float2* K2 = (const float2*)Kw;
    const float2* Q2 = (const float2*)Qw;
    __nv_bfloat16 hx, lx, hy, ly;
    float2 v = K2[i];
    bsplit(v.x, hx, lx); bsplit(v.y, hy, ly);
    *(__nv_bfloat162*)&gKQ[0 * PLANE_E + r * P + c] = __halves2bfloat162(hx, hy);
    *(__nv_bfloat162*)&gKQ[1 * PLANE_E + r * P + c] = __halves2bfloat162(lx, ly);
    float2 u = Q2[i];
    *(__nv_bfloat162*)&gKQ[2 * PLANE_E + r * P + c] =
        __halves2bfloat162(__float2bfloat16_rn(u.x), __float2bfloat16_rn(u.y));
}

__global__ __launch_bounds__(256, 4)
void SAM3E_kernel(const float* __restrict__ Fg,
                  float* __restrict__ outg)
{
    extern __shared__ __nv_bfloat16 sb[];
    const unsigned sbase = (unsigned)__cvta_generic_to_shared(sb);
    __nv_bfloat16* sFh = sb;
    __nv_bfloat16* sFl = sb + 1*PLANE_E;
    __nv_bfloat16* sGh = sb + 2*PLANE_E;   // = Kh region, reused after sync1
    __nv_bfloat16* sGl = sb + 3*PLANE_E;
    __nv_bfloat16* sHh = sb + 4*PLANE_E;   // = Qh region
    __nv_bfloat16* sHl = sb + 5*PLANE_E;   // = X

    const int b   = blockIdx.x;
    const int tid = threadIdx.x;

    // ---- stage F (float4 loads, split, packed uint2 stores) ----
    const float4* F4 = (const float4*)(Fg + (size_t)b * BTOK);
    for (int i = tid; i < 800; i += 256) {
        float4 v = F4[i];
        int n = i >> 4, d = (i & 15) << 2;
        __nv_bfloat16 h0,l0,h1,l1,h2,l2,h3,l3;
        bsplit(v.x, h0, l0); bsplit(v.y, h1, l1);
        bsplit(v.z, h2, l2); bsplit(v.w, h3, l3);
        __nv_bfloat162 ph0 = __halves2bfloat162(h0, h1), ph1 = __halves2bfloat162(h2, h3);
        __nv_bfloat162 pl0 = __halves2bfloat162(l0, l1), pl1 = __halves2bfloat162(l2, l3);
        uint2 uh, ul;
        uh.x = *(unsigned*)&ph0; uh.y = *(unsigned*)&ph1;
        ul.x = *(unsigned*)&pl0; ul.y = *(unsigned*)&pl1;
        *(uint2*)&sFh[n * P + d] = uh;
        *(uint2*)&sFl[n * P + d] = ul;
    }
    for (int i = tid; i < 14 * (P / 2); i += 256) {     // zero-pad rows 50..63
        int off = 50 * P + 2 * i;
        *(unsigned*)&sFh[off] = 0u;
        *(unsigned*)&sFl[off] = 0u;
    }
    // ---- stage pre-split K/Q planes with one linear uint4 copy ----
    {
        const uint4* src = (const uint4*)gKQ;
        uint4* dst = (uint4*)(sb + 2 * PLANE_E);        // Kh,Kl,Qh contiguous
        #pragma unroll 2
        for (int i = tid; i < 3 * PLANE_B / 16; i += 256)
            dst[i] = src[i];
    }
    __syncthreads();

    const int lane = tid & 31, w = tid >> 5;
    const int m0 = (w >> 1) * 16;           // 16-row band
    const int n0 = (w & 1) * 32;            // 32-col half (4 n8-tiles)
    const int q   = lane & 7;
    const int b8  = (lane >> 3) & 1;
    const int b16 = (lane >> 4) & 1;
    const int g   = lane >> 2, t4 = lane & 3;

    // ========== Phase A2: H = F @ K_w (3-term), QF = F @ Q_w^T (1-term) ==========
    float accH[4][4] = {};
    float accQ[4][4] = {};
    {
        const unsigned a2 = sbase + OFF_FH + 2u * ((m0 + 8 * b8 + q) * P + 8 * b16);
        const unsigned bk = sbase + OFF_KH + 2u * ((8 * b8 + q) * P + n0 + 8 * b16);
        const unsigned bq = sbase + OFF_QH + 2u * ((n0 + q + 8 * b16) * P + 8 * b8);
        #pragma unroll
        for (int kk = 0; kk < 4; ++kk) {
            unsigned ah[4], al[4];
            ldsm_x4(ah, a2 + kk * 32);
            ldsm_x4(al, a2 + kk * 32 + PLANE_B);
            #pragma unroll
            for (int p = 0; p < 2; ++p) {
                unsigned bh[4], bl[4];
                ldsm_x4t(bh, bk + kk * 16 * PB + p * 32);
                ldsm_x4t(bl, bk + kk * 16 * PB + p * 32 + PLANE_B);
                mma16(accH[2*p  ], ah, bh    );
                mma16(accH[2*p  ], al, bh    );
                mma16(accH[2*p  ], ah, bl    );
                mma16(accH[2*p+1], ah, bh + 2);
                mma16(accH[2*p+1], al, bh + 2);
                mma16(accH[2*p+1], ah, bl + 2);
                unsigned bq4[4];
                ldsm_x4(bq4, bq + kk * 32 + p * 16 * PB);
                mma16(accQ[2*p  ], ah, bq4    );
                mma16(accQ[2*p+1], ah, bq4 + 2);
            }
        }
    }
    __syncthreads();   // all K/Q reads done -> regions reusable

    // store H (split) into Q-region planes
    #pragma unroll
    for (int t = 0; t < 4; ++t) {
        const int col = n0 + 8 * t + 2 * t4;
        __nv_bfloat16 h0,l0,h1,l1,h2,l2,h3,l3;
        bsplit(accH[t][0],h0,l0); bsplit(accH[t][1],h1,l1);
        bsplit(accH[t][2],h2,l2); bsplit(accH[t][3],h3,l3);
        *(__nv_bfloat162*)&sHh[(m0 + g    ) * P + col] = __halves2bfloat162(h0, h1);
        *(__nv_bfloat162*)&sHl[(m0 + g    ) * P + col] = __halves2bfloat162(l0, l1);
        *(__nv_bfloat162*)&sHh[(m0 + g + 8) * P + col] = __halves2bfloat162(h2, h3);
        *(__nv_bfloat162*)&sHl[(m0 + g + 8) * P + col] = __halves2bfloat162(l2, l3);
    }

    // ========== Phase A1: G = F^T F (reads F only), store into K-region ==========
    {
        float accG[4][4] = {};
        const unsigned a1 = sbase + OFF_FH + 2u * ((8 * b16 + q) * P + m0 + 8 * b8);
        const unsigned b1 = sbase + OFF_FH + 2u * ((8 * b8 + q) * P + n0 + 8 * b16);
        #pragma unroll
        for (int kk = 0; kk < 4; ++kk) {
            unsigned ah[4], al[4];
            ldsm_x4t(ah, a1 + kk * 16 * PB);
            ldsm_x4t(al, a1 + kk * 16 * PB + PLANE_B);
            #pragma unroll
            for (int p = 0; p < 2; ++p) {
                unsigned bh[4], bl[4];
                ldsm_x4t(bh, b1 + kk * 16 * PB + p * 32);
                ldsm_x4t(bl, b1 + kk * 16 * PB + p * 32 + PLANE_B);
                mma16(accG[2*p  ], ah, bh    );
                mma16(accG[2*p  ], al, bh    );
                mma16(accG[2*p  ], ah, bl    );
                mma16(accG[2*p+1], ah, bh + 2);
                mma16(accG[2*p+1], al, bh + 2);
                mma16(accG[2*p+1], ah, bl + 2);
            }
        }
        #pragma unroll
        for (int t = 0; t < 4; ++t) {
            const int col = n0 + 8 * t + 2 * t4;
            __nv_bfloat16 h0,l0,h1,l1,h2,l2,h3,l3;
            bsplit(accG[t][0],h0,l0); bsplit(accG[t][1],h1,l1);
            bsplit(accG[t][2],h2,l2); bsplit(accG[t][3],h3,l3);
            *(__nv_bfloat162*)&sGh[(m0 + g    ) * P + col] = __halves2bfloat162(h0, h1);
            *(__nv_bfloat162*)&sGl[(m0 + g    ) * P + col] = __halves2bfloat162(l0, l1);
            *(__nv_bfloat162*)&sGh[(m0 + g + 8) * P + col] = __halves2bfloat162(h2, h3);
            *(__nv_bfloat162*)&sGl[(m0 + g + 8) * P + col] = __halves2bfloat162(l2, l3);
        }
    }
    __syncthreads();   // G + H stores visible

    // ========== Phase B: T = H @ G  (B reads G rows via symmetry, non-trans) ==========
    float accT[4][4] = {};
    {
        const unsigned a3 = sbase + OFF_QH + 2u * ((m0 + 8 * b8 + q) * P + 8 * b16);  // H planes
        const unsigned b3 = sbase + OFF_KH + 2u * ((n0 + q + 8 * b16) * P + 8 * b8);  // G planes
        #pragma unroll
        for (int kk = 0; kk < 4; ++kk) {
            unsigned ah[4], al[4];
            ldsm_x4(ah, a3 + kk * 32);
            ldsm_x4(al, a3 + kk * 32 + PLANE_B);
            #pragma unroll
            for (int p = 0; p < 2; ++p) {
                unsigned bh[4], bl[4];
                ldsm_x4(bh, b3 + kk * 32 + p * 16 * PB);
                ldsm_x4(bl, b3 + kk * 32 + p * 16 * PB + PLANE_B);
                mma16(accT[2*p  ], ah, bh    );
                mma16(accT[2*p  ], al, bh    );
                mma16(accT[2*p  ], ah, bl    );
                mma16(accT[2*p+1], ah, bh + 2);
                mma16(accT[2*p+1], al, bh + 2);
                mma16(accT[2*p+1], ah, bl + 2);
            }
        }
    }

    // ========== Epilogue: out = F .* T + QF  (rows < 50) ==========
    float* ob = outg + (size_t)b * BTOK;
    const int r1 = m0 + g;
    const int r2 = m0 + g + 8;
    #pragma unroll
    for (int t = 0; t < 4; ++t) {
        const int col = n0 + 8 * t + 2 * t4;
        if (r1 < NTOK) {
            float2 fh = __bfloat1622float2(*(__nv_bfloat162*)&sFh[r1 * P + col]);
            float2 fl = __bfloat1622float2(*(__nv_bfloat162*)&sFl[r1 * P + col]);
            float2 o;
            o.x = (fh.x + fl.x) * accT[t][0] + accQ[t][0];
            o.y = (fh.y + fl.y) * accT[t][1] + accQ[t][1];
            *(float2*)&ob[r1 * 64 + col] = o;
        }
        if (r2 < NTOK) {
            float2 fh = __bfloat1622float2(*(__nv_bfloat162*)&sFh[r2 * P + col]);
            float2 fl = __bfloat1622float2(*(__nv_bfloat162*)&sFl[r2 * P + col]);
            float2 o;
            o.x = (fh.x + fl.x) * accT[t][2] + accQ[t][2];
            o.y = (fh.y + fl.y) * accT[t][3] + accQ[t][3];
            *(float2*)&ob[r2 * 64 + col] = o;
        }
    }
}

extern "C" void kernel_launch(void* const* d_in, const int* in_sizes, int n_in,
                              void* d_out, int out_size)
{
    const float* F  = (const float*)d_in[0];
    const float* Kw = (const float*)d_in[1];
    const float* Qw = (const float*)d_in[2];
    float* out      = (float*)d_out;

    const int B = in_sizes[0] / BTOK;                   // 8192

    cudaFuncSetAttribute(SAM3E_kernel,
                         cudaFuncAttributeMaxDynamicSharedMemorySize, SMEM_BYTES);

    SAM3E_prep<<<8, 256>>>(Kw, Qw);
    SAM3E_kernel<<<B, 256, SMEM_BYTES>>>(F, out);
}

// round 13
// speedup vs baseline: 1.2302x; 1.0150x over previous
#include <cuda_runtime.h>
#include <cuda_bf16.h>

#define NTOK 50
#define BTOK 3200
#define P    72                 // plane pitch in bf16 elems (144B rows; LDSM conflict-free)
#define PB   (P*2)              // 144 B
#define PLANE_E (64*P)
#define PLANE_B (64*PB)         // 9216 B

// 6 planes: Fh Fl Kh Kl Qh X ; G aliases Kh/Kl, H aliases Qh/X (after barriers)
#define OFF_FH 0
#define OFF_FL (1*PLANE_B)
#define OFF_KH (2*PLANE_B)      // -> Gh
#define OFF_KL (3*PLANE_B)      // -> Gl
#define OFF_QH (4*PLANE_B)      // -> Hh
#define OFF_X  (5*PLANE_B)      // -> Hl
#define SMEM_BYTES (6*PLANE_B)  // 55,296 B -> 4 CTAs/SM

// pre-split weight planes (Kh, Kl, Qh) in pitch-P layout, ready for linear copy
__device__ __align__(16) __nv_bfloat16 gKQ[3 * PLANE_E];

__device__ __forceinline__ void ldsm_x4(unsigned* r, unsigned a) {
    asm volatile("ldmatrix.sync.aligned.m8n8.x4.shared.b16 {%0,%1,%2,%3}, [%4];"
                 : "=r"(r[0]), "=r"(r[1]), "=r"(r[2]), "=r"(r[3]) : "r"(a));
}
__device__ __forceinline__ void ldsm_x4t(unsigned* r, unsigned a) {
    asm volatile("ldmatrix.sync.aligned.m8n8.x4.trans.shared.b16 {%0,%1,%2,%3}, [%4];"
                 : "=r"(r[0]), "=r"(r[1]), "=r"(r[2]), "=r"(r[3]) : "r"(a));
}
__device__ __forceinline__ void mma16(float* d, const unsigned* a, const unsigned* b) {
    asm volatile(
        "mma.sync.aligned.m16n8k16.row.col.f32.bf16.bf16.f32 "
        "{%0,%1,%2,%3}, {%4,%5,%6,%7}, {%8,%9}, {%0,%1,%2,%3};\n"
        : "+f"(d[0]), "+f"(d[1]), "+f"(d[2]), "+f"(d[3])
        : "r"(a[0]), "r"(a[1]), "r"(a[2]), "r"(a[3]), "r"(b[0]), "r"(b[1]));
}
__device__ __forceinline__ void bsplit(float x, __nv_bfloat16& h, __nv_bfloat16& l) {
    h = __float2bfloat16_rn(x);
    l = __float2bfloat16_rn(x - __bfloat162float(h));
}

// ---- prep: split K_w/Q_w once per launch into gKQ planes ----
__global__ void SAM3E_prep(const float* __restrict__ Kw, const float* __restrict__ Qw)
{
    const int i = blockIdx.x * 256 + threadIdx.x;   // 0..2047, each handles 2 elems
    const int r = i >> 5, c = (i & 31) << 1;
    const float2* K2 = (const float2*)Kw;
    const float2* Q2 = (const float2*)Qw;
    __nv_bfloat16 hx, lx, hy, ly;
    float2 v = K2[i];
    bsplit(v.x, hx, lx); bsplit(v.y, hy, ly);
    *(__nv_bfloat162*)&gKQ[0 * PLANE_E + r * P + c] = __halves2bfloat162(hx, hy);
    *(__nv_bfloat162*)&gKQ[1 * PLANE_E + r * P + c] = __halves2bfloat162(lx, ly);
    float2 u = Q2[i];
    *(__nv_bfloat162*)&gKQ[2 * PLANE_E + r * P + c] =
        __halves2bfloat162(__float2bfloat16_rn(u.x), __float2bfloat16_rn(u.y));
}

__global__ __launch_bounds__(256, 4)
void SAM3E_kernel(const float* __restrict__ Fg,
                  float* __restrict__ outg)
{
    extern __shared__ __nv_bfloat16 sb[];
    const unsigned sbase = (unsigned)__cvta_generic_to_shared(sb);
    __nv_bfloat16* sFh = sb;
    __nv_bfloat16* sFl = sb + 1*PLANE_E;
    __nv_bfloat16* sGh = sb + 2*PLANE_E;   // = Kh region, reused after sync1
    __nv_bfloat16* sGl = sb + 3*PLANE_E;
    __nv_bfloat16* sHh = sb + 4*PLANE_E;   // = Qh region
    __nv_bfloat16* sHl = sb + 5*PLANE_E;   // = X

    const int b   = blockIdx.x;
    const int tid = threadIdx.x;

    // ---- stage F (float4 loads, split, packed uint2 stores) ----
    const float4* F4 = (const float4*)(Fg + (size_t)b * BTOK);
    for (int i = tid; i < 800; i += 256) {
        float4 v = F4[i];
        int n = i >> 4, d = (i & 15) << 2;
        __nv_bfloat16 h0,l0,h1,l1,h2,l2,h3,l3;
        bsplit(v.x, h0, l0); bsplit(v.y, h1, l1);
        bsplit(v.z, h2, l2); bsplit(v.w, h3, l3);
        __nv_bfloat162 ph0 = __halves2bfloat162(h0, h1), ph1 = __halves2bfloat162(h2, h3);
        __nv_bfloat162 pl0 = __halves2bfloat162(l0, l1), pl1 = __halves2bfloat162(l2, l3);
        uint2 uh, ul;
        uh.x = *(unsigned*)&ph0; uh.y = *(unsigned*)&ph1;
        ul.x = *(unsigned*)&pl0; ul.y = *(unsigned*)&pl1;
        *(uint2*)&sFh[n * P + d] = uh;
        *(uint2*)&sFl[n * P + d] = ul;
    }
    for (int i = tid; i < 14 * (P / 2); i += 256) {     // zero-pad rows 50..63
        int off = 50 * P + 2 * i;
        *(unsigned*)&sFh[off] = 0u;
        *(unsigned*)&sFl[off] = 0u;
    }
    // ---- stage pre-split K/Q planes with one linear uint4 copy ----
    {
        const uint4* src = (const uint4*)gKQ;
        uint4* dst = (uint4*)(sb + 2 * PLANE_E);        // Kh,Kl,Qh contiguous
        #pragma unroll 2
        for (int i = tid; i < 3 * PLANE_B / 16; i += 256)
            dst[i] = src[i];
    }
    __syncthreads();

    const int lane = tid & 31, w = tid >> 5;
    const int m0 = (w >> 1) * 16;           // 16-row band (A2/B/epilogue)
    const int n0 = (w & 1) * 32;            // 32-col half
    const int q   = lane & 7;
    const int b8  = (lane >> 3) & 1;
    const int b16 = (lane >> 4) & 1;
    const int g   = lane >> 2, t4 = lane & 3;

    // ========== Phase A2: H = F @ K_w (3-term), QF = F @ Q_w^T (1-term) ==========
    float accH[4][4] = {};
    float accQ[4][4] = {};
    {
        const unsigned a2 = sbase + OFF_FH + 2u * ((m0 + 8 * b8 + q) * P + 8 * b16);
        const unsigned bk = sbase + OFF_KH + 2u * ((8 * b8 + q) * P + n0 + 8 * b16);
        const unsigned bq = sbase + OFF_QH + 2u * ((n0 + q + 8 * b16) * P + 8 * b8);
        #pragma unroll
        for (int kk = 0; kk < 4; ++kk) {
            unsigned ah[4], al[4];
            ldsm_x4(ah, a2 + kk * 32);
            ldsm_x4(al, a2 + kk * 32 + PLANE_B);
            #pragma unroll
            for (int p = 0; p < 2; ++p) {
                unsigned bh[4], bl[4];
                ldsm_x4t(bh, bk + kk * 16 * PB + p * 32);
                ldsm_x4t(bl, bk + kk * 16 * PB + p * 32 + PLANE_B);
                mma16(accH[2*p  ], ah, bh    );
                mma16(accH[2*p  ], al, bh    );
                mma16(accH[2*p  ], ah, bl    );
                mma16(accH[2*p+1], ah, bh + 2);
                mma16(accH[2*p+1], al, bh + 2);
                mma16(accH[2*p+1], ah, bl + 2);
                unsigned bq4[4];
                ldsm_x4(bq4, bq + kk * 32 + p * 16 * PB);
                mma16(accQ[2*p  ], ah, bq4    );
                mma16(accQ[2*p+1], ah, bq4 + 2);
            }
        }
    }
    __syncthreads();   // all K/Q reads done -> regions reusable

    // store H (split) into Q-region planes
    #pragma unroll
    for (int t = 0; t < 4; ++t) {
        const int col = n0 + 8 * t + 2 * t4;
        __nv_bfloat16 h0,l0,h1,l1,h2,l2,h3,l3;
        bsplit(accH[t][0],h0,l0); bsplit(accH[t][1],h1,l1);
        bsplit(accH[t][2],h2,l2); bsplit(accH[t][3],h3,l3);
        *(__nv_bfloat162*)&sHh[(m0 + g    ) * P + col] = __halves2bfloat162(h0, h1);
        *(__nv_bfloat162*)&sHl[(m0 + g    ) * P + col] = __halves2bfloat162(l0, l1);
        *(__nv_bfloat162*)&sHh[(m0 + g + 8) * P + col] = __halves2bfloat162(h2, h3);
        *(__nv_bfloat162*)&sHl[(m0 + g + 8) * P + col] = __halves2bfloat162(l2, l3);
    }

    // ========== Phase A1: G = F^T F — symmetric, 6 of 8 tiles computed ==========
    // tiles (band,half): w0:(0,0) w1:(1,0) w2:(2,0) w3:(3,0) w4:(2,1) w5:(3,1); w6,w7 idle.
    // Missing region G[0:32, 32:64] = transpose of tiles (2,0),(3,0) -> mirror stores by w2,w3.
    if (w < 6) {
        const int gm0 = 16 * (w < 4 ? w : w - 2);
        const int gn0 = (w < 4) ? 0 : 32;
        const bool mirror = (w == 2 || w == 3);
        float accG[4][4] = {};
        const unsigned a1 = sbase + OFF_FH + 2u * ((8 * b16 + q) * P + gm0 + 8 * b8);
        const unsigned b1 = sbase + OFF_FH + 2u * ((8 * b8 + q) * P + gn0 + 8 * b16);
        #pragma unroll
        for (int kk = 0; kk < 4; ++kk) {
            unsigned ah[4], al[4];
            ldsm_x4t(ah, a1 + kk * 16 * PB);
            ldsm_x4t(al, a1 + kk * 16 * PB + PLANE_B);
            #pragma unroll
            for (int p = 0; p < 2; ++p) {
                unsigned bh[4], bl[4];
                ldsm_x4t(bh, b1 + kk * 16 * PB + p * 32);
                ldsm_x4t(bl, b1 + kk * 16 * PB + p * 32 + PLANE_B);
                mma16(accG[2*p  ], ah, bh    );
                mma16(accG[2*p  ], al, bh    );
                mma16(accG[2*p  ], ah, bl    );
                mma16(accG[2*p+1], ah, bh + 2);
                mma16(accG[2*p+1], al, bh + 2);
                mma16(accG[2*p+1], ah, bl + 2);
            }
        }
        #pragma unroll
        for (int t = 0; t < 4; ++t) {
            const int col = gn0 + 8 * t + 2 * t4;
            __nv_bfloat16 h0,l0,h1,l1,h2,l2,h3,l3;
            bsplit(accG[t][0],h0,l0); bsplit(accG[t][1],h1,l1);
            bsplit(accG[t][2],h2,l2); bsplit(accG[t][3],h3,l3);
            const int r1 = gm0 + g, r2 = gm0 + g + 8;
            *(__nv_bfloat162*)&sGh[r1 * P + col] = __halves2bfloat162(h0, h1);
            *(__nv_bfloat162*)&sGl[r1 * P + col] = __halves2bfloat162(l0, l1);
            *(__nv_bfloat162*)&sGh[r2 * P + col] = __halves2bfloat162(h2, h3);
            *(__nv_bfloat162*)&sGl[r2 * P + col] = __halves2bfloat162(l2, l3);
            if (mirror) {      // transposed copy into G[0:32, 32:64]
                sGh[(col    ) * P + r1] = h0;  sGl[(col    ) * P + r1] = l0;
                sGh[(col + 1) * P + r1] = h1;  sGl[(col + 1) * P + r1] = l1;
                sGh[(col    ) * P + r2] = h2;  sGl[(col    ) * P + r2] = l2;
                sGh[(col + 1) * P + r2] = h3;  sGl[(col + 1) * P + r2] = l3;
            }
        }
    }
    __syncthreads();   // G + H stores visible

    // ========== Phase B: T = H @ G  (B reads G rows via symmetry, non-trans) ==========
    float accT[4][4] = {};
    {
        const unsigned a3 = sbase + OFF_QH + 2u * ((m0 + 8 * b8 + q) * P + 8 * b16);  // H planes
        const unsigned b3 = sbase + OFF_KH + 2u * ((n0 + q + 8 * b16) * P + 8 * b8);  // G planes
        #pragma unroll
        for (int kk = 0; kk < 4; ++kk) {
            unsigned ah[4], al[4];
            ldsm_x4(ah, a3 + kk * 32);
            ldsm_x4(al, a3 + kk * 32 + PLANE_B);
            #pragma unroll
            for (int p = 0; p < 2; ++p) {
                unsigned bh[4], bl[4];
                ldsm_x4(bh, b3 + kk * 32 + p * 16 * PB);
                ldsm_x4(bl, b3 + kk * 32 + p * 16 * PB + PLANE_B);
                mma16(accT[2*p  ], ah, bh    );
                mma16(accT[2*p  ], al, bh    );
                mma16(accT[2*p  ], ah, bl    );
                mma16(accT[2*p+1], ah, bh + 2);
                mma16(accT[2*p+1], al, bh + 2);
                mma16(accT[2*p+1], ah, bl + 2);
            }
        }
    }

    // ========== Epilogue: out = F .* T + QF  (rows < 50) ==========
    float* ob = outg + (size_t)b * BTOK;
    const int r1 = m0 + g;
    const int r2 = m0 + g + 8;
    #pragma unroll
    for (int t = 0; t < 4; ++t) {
        const int col = n0 + 8 * t + 2 * t4;
        if (r1 < NTOK) {
            float2 fh = __bfloat1622float2(*(__nv_bfloat162*)&sFh[r1 * P + col]);
            float2 fl = __bfloat1622float2(*(__nv_bfloat162*)&sFl[r1 * P + col]);
            float2 o;
            o.x = (fh.x + fl.x) * accT[t][0] + accQ[t][0];
            o.y = (fh.y + fl.y) * accT[t][1] + accQ[t][1];
            *(float2*)&ob[r1 * 64 + col] = o;
        }
        if (r2 < NTOK) {
            float2 fh = __bfloat1622float2(*(__nv_bfloat162*)&sFh[r2 * P + col]);
            float2 fl = __bfloat1622float2(*(__nv_bfloat162*)&sFl[r2 * P + col]);
            float2 o;
            o.x = (fh.x + fl.x) * accT[t][2] + accQ[t][2];
            o.y = (fh.y + fl.y) * accT[t][3] + accQ[t][3];
            *(float2*)&ob[r2 * 64 + col] = o;
        }
    }
}

extern "C" void kernel_launch(void* const* d_in, const int* in_sizes, int n_in,
                              void* d_out, int out_size)
{
    const float* F  = (const float*)d_in[0];
    const float* Kw = (const float*)d_in[1];
    const float* Qw = (const float*)d_in[2];
    float* out      = (float*)d_out;

    const int B = in_sizes[0] / BTOK;                   // 8192

    cudaFuncSetAttribute(SAM3E_kernel,
                         cudaFuncAttributeMaxDynamicSharedMemorySize, SMEM_BYTES);

    SAM3E_prep<<<8, 256>>>(Kw, Qw);
    SAM3E_kernel<<<B, 256, SMEM_BYTES>>>(F, out);
}

// round 14
// speedup vs baseline: 1.2509x; 1.0168x over previous
#include <cuda_runtime.h>
#include <cuda_bf16.h>

#define NTOK 50
#define BTOK 3200
#define P    72                 // plane pitch in bf16 elems (144B rows; LDSM conflict-free)
#define PB   (P*2)              // 144 B
#define PLANE_E (64*P)
#define PLANE_B (64*PB)         // 9216 B

// 6 dedicated planes: Fh Fl Gh Gl Hh Hl
#define OFF_FH 0
#define OFF_FL (1*PLANE_B)
#define OFF_GH (2*PLANE_B)
#define OFF_GL (3*PLANE_B)
#define OFF_HH (4*PLANE_B)
#define OFF_HL (5*PLANE_B)
#define SMEM_BYTES (6*PLANE_B)  // 55,296 B -> 4 CTAs/SM

// weight B-fragments in register layout: [Kh 16][Kl 16][Q 16] sets x 32 lanes x uint4
__device__ __align__(16) uint4 gFrag[48 * 32];

__device__ __forceinline__ void ldsm_x4(unsigned* r, unsigned a) {
    asm volatile("ldmatrix.sync.aligned.m8n8.x4.shared.b16 {%0,%1,%2,%3}, [%4];"
                 : "=r"(r[0]), "=r"(r[1]), "=r"(r[2]), "=r"(r[3]) : "r"(a));
}
__device__ __forceinline__ void ldsm_x4t(unsigned* r, unsigned a) {
    asm volatile("ldmatrix.sync.aligned.m8n8.x4.trans.shared.b16 {%0,%1,%2,%3}, [%4];"
                 : "=r"(r[0]), "=r"(r[1]), "=r"(r[2]), "=r"(r[3]) : "r"(a));
}
__device__ __forceinline__ void mma16(float* d, const unsigned* a, const unsigned* b) {
    asm volatile(
        "mma.sync.aligned.m16n8k16.row.col.f32.bf16.bf16.f32 "
        "{%0,%1,%2,%3}, {%4,%5,%6,%7}, {%8,%9}, {%0,%1,%2,%3};\n"
        : "+f"(d[0]), "+f"(d[1]), "+f"(d[2]), "+f"(d[3])
        : "r"(a[0]), "r"(a[1]), "r"(a[2]), "r"(a[3]), "r"(b[0]), "r"(b[1]));
}
__device__ __forceinline__ void bsplit(float x, __nv_bfloat16& h, __nv_bfloat16& l) {
    h = __float2bfloat16_rn(x);
    l = __float2bfloat16_rn(x - __bfloat162float(h));
}

// ---- prep: split weights, then REPLAY the exact ldsm loads and store fragments ----
__global__ void SAM3E_prep(const float* __restrict__ Kw, const float* __restrict__ Qw)
{
    __shared__ __nv_bfloat16 sw[3 * PLANE_E];        // Kh, Kl, Qh planes
    const int tid = threadIdx.x;
    const float2* K2 = (const float2*)Kw;
    const float2* Q2 = (const float2*)Qw;
    for (int i = tid; i < 2048; i += 256) {
        int r = i >> 5, c = (i & 31) << 1;
        __nv_bfloat16 hx, lx, hy, ly;
        float2 v = K2[i];
        bsplit(v.x, hx, lx); bsplit(v.y, hy, ly);
        *(__nv_bfloat162*)&sw[0 * PLANE_E + r * P + c] = __halves2bfloat162(hx, hy);
        *(__nv_bfloat162*)&sw[1 * PLANE_E + r * P + c] = __halves2bfloat162(lx, ly);
        float2 u = Q2[i];
        *(__nv_bfloat162*)&sw[2 * PLANE_E + r * P + c] =
            __halves2bfloat162(__float2bfloat16_rn(u.x), __float2bfloat16_rn(u.y));
    }
    __syncthreads();
    const unsigned sbase = (unsigned)__cvta_generic_to_shared(sw);
    const int w = tid >> 5, lane = tid & 31;
    const int q = lane & 7, b8 = (lane >> 3) & 1, b16 = (lane >> 4) & 1;
    for (int s = w; s < 48; s += 8) {
        const int kind = s >> 4;          // 0 Kh, 1 Kl, 2 Qh
        const int kk = (s >> 2) & 3, ct = s & 3;
        unsigned r[4];
        if (kind < 2) {                   // trans read, exactly main's old K path
            unsigned a = sbase + kind * PLANE_B
                       + 2u * ((kk * 16 + 8 * b8 + q) * P + ct * 16 + 8 * b16);
            ldsm_x4t(r, a);
        } else {                          // non-trans read, exactly main's old Q path
            unsigned a = sbase + 2 * PLANE_B
                       + 2u * ((ct * 16 + q + 8 * b16) * P + kk * 16 + 8 * b8);
            ldsm_x4(r, a);
        }
        gFrag[s * 32 + lane] = make_uint4(r[0], r[1], r[2], r[3]);
    }
}

__global__ __launch_bounds__(256, 4)
void SAM3E_kernel(const float* __restrict__ Fg,
                  float* __restrict__ outg)
{
    extern __shared__ __nv_bfloat16 sb[];
    const unsigned sbase = (unsigned)__cvta_generic_to_shared(sb);
    __nv_bfloat16* sFh = sb;
    __nv_bfloat16* sFl = sb + 1 * PLANE_E;
    __nv_bfloat16* sGh = sb + 2 * PLANE_E;
    __nv_bfloat16* sGl = sb + 3 * PLANE_E;
    __nv_bfloat16* sHh = sb + 4 * PLANE_E;
    __nv_bfloat16* sHl = sb + 5 * PLANE_E;

    const int b   = blockIdx.x;
    const int tid = threadIdx.x;

    // ---- stage F (float4 loads, split, packed uint2 stores) ----
    const float4* F4 = (const float4*)(Fg + (size_t)b * BTOK);
    for (int i = tid; i < 800; i += 256) {
        float4 v = F4[i];
        int n = i >> 4, d = (i & 15) << 2;
        __nv_bfloat16 h0,l0,h1,l1,h2,l2,h3,l3;
        bsplit(v.x, h0, l0); bsplit(v.y, h1, l1);
        bsplit(v.z, h2, l2); bsplit(v.w, h3, l3);
        __nv_bfloat162 ph0 = __halves2bfloat162(h0, h1), ph1 = __halves2bfloat162(h2, h3);
        __nv_bfloat162 pl0 = __halves2bfloat162(l0, l1), pl1 = __halves2bfloat162(l2, l3);
        uint2 uh, ul;
        uh.x = *(unsigned*)&ph0; uh.y = *(unsigned*)&ph1;
        ul.x = *(unsigned*)&pl0; ul.y = *(unsigned*)&pl1;
        *(uint2*)&sFh[n * P + d] = uh;
        *(uint2*)&sFl[n * P + d] = ul;
    }
    for (int i = tid; i < 14 * (P / 2); i += 256) {     // zero-pad rows 50..63
        int off = 50 * P + 2 * i;
        *(unsigned*)&sFh[off] = 0u;
        *(unsigned*)&sFl[off] = 0u;
    }
    __syncthreads();

    const int lane = tid & 31, w = tid >> 5;
    const int m0 = (w >> 1) * 16;           // 16-row band (A2/B/epilogue)
    const int n0 = (w & 1) * 32;            // 32-col half
    const int q   = lane & 7;
    const int b8  = (lane >> 3) & 1;
    const int b16 = (lane >> 4) & 1;
    const int g   = lane >> 2, t4 = lane & 3;

    const uint4* __restrict__ fKh = gFrag;
    const uint4* __restrict__ fKl = gFrag + 16 * 32;
    const uint4* __restrict__ fQ  = gFrag + 32 * 32;

    // ========== Phase A2: H = F @ K_w (3-term), QF = F @ Q_w^T (1-term) ==========
    float accH[4][4] = {};
    float accQ[4][4] = {};
    {
        const unsigned a2 = sbase + OFF_FH + 2u * ((m0 + 8 * b8 + q) * P + 8 * b16);
        #pragma unroll
        for (int kk = 0; kk < 4; ++kk) {
            unsigned ah[4], al[4];
            ldsm_x4(ah, a2 + kk * 32);
            ldsm_x4(al, a2 + kk * 32 + PLANE_B);
            #pragma unroll
            for (int p = 0; p < 2; ++p) {
                const int fi = (kk * 4 + (n0 >> 4) + p) * 32 + lane;
                uint4 bhv = fKh[fi], blv = fKl[fi], bqv = fQ[fi];
                const unsigned* bh = (const unsigned*)&bhv;
                const unsigned* bl = (const unsigned*)&blv;
                const unsigned* bq = (const unsigned*)&bqv;
                mma16(accH[2*p  ], ah, bh    );
                mma16(accH[2*p  ], al, bh    );
                mma16(accH[2*p  ], ah, bl    );
                mma16(accH[2*p+1], ah, bh + 2);
                mma16(accH[2*p+1], al, bh + 2);
                mma16(accH[2*p+1], ah, bl + 2);
                mma16(accQ[2*p  ], ah, bq    );
                mma16(accQ[2*p+1], ah, bq + 2);
            }
        }
    }

    // store H (split) into dedicated planes — no barrier needed (fresh planes)
    #pragma unroll
    for (int t = 0; t < 4; ++t) {
        const int col = n0 + 8 * t + 2 * t4;
        __nv_bfloat16 h0,l0,h1,l1,h2,l2,h3,l3;
        bsplit(accH[t][0],h0,l0); bsplit(accH[t][1],h1,l1);
        bsplit(accH[t][2],h2,l2); bsplit(accH[t][3],h3,l3);
        *(__nv_bfloat162*)&sHh[(m0 + g    ) * P + col] = __halves2bfloat162(h0, h1);
        *(__nv_bfloat162*)&sHl[(m0 + g    ) * P + col] = __halves2bfloat162(l0, l1);
        *(__nv_bfloat162*)&sHh[(m0 + g + 8) * P + col] = __halves2bfloat162(h2, h3);
        *(__nv_bfloat162*)&sHl[(m0 + g + 8) * P + col] = __halves2bfloat162(l2, l3);
    }

    // ========== Phase A1: G = F^T F — symmetric, 6 of 8 tiles, NO mirror ==========
    // tiles: w0:(rows0-15,c0-31) w1:(16-31,0-31) w2:(32-47,0-31) w3:(48-63,0-31)
    //        w4:(32-47,32-63) w5:(48-63,32-63); w6,w7 idle.
    if (w < 6) {
        const int gm0 = 16 * (w < 4 ? w : w - 2);
        const int gn0 = (w < 4) ? 0 : 32;
        float accG[4][4] = {};
        const unsigned a1 = sbase + OFF_FH + 2u * ((8 * b16 + q) * P + gm0 + 8 * b8);
        const unsigned b1 = sbase + OFF_FH + 2u * ((8 * b8 + q) * P + gn0 + 8 * b16);
        #pragma unroll
        for (int kk = 0; kk < 4; ++kk) {
            unsigned ah[4], al[4];
            ldsm_x4t(ah, a1 + kk * 16 * PB);
            ldsm_x4t(al, a1 + kk * 16 * PB + PLANE_B);
            #pragma unroll
            for (int p = 0; p < 2; ++p) {
                unsigned bh[4], bl[4];
                ldsm_x4t(bh, b1 + kk * 16 * PB + p * 32);
                ldsm_x4t(bl, b1 + kk * 16 * PB + p * 32 + PLANE_B);
                mma16(accG[2*p  ], ah, bh    );
                mma16(accG[2*p  ], al, bh    );
                mma16(accG[2*p  ], ah, bl    );
                mma16(accG[2*p+1], ah, bh + 2);
                mma16(accG[2*p+1], al, bh + 2);
                mma16(accG[2*p+1], ah, bl + 2);
            }
        }
        #pragma unroll
        for (int t = 0; t < 4; ++t) {
            const int col = gn0 + 8 * t + 2 * t4;
            __nv_bfloat16 h0,l0,h1,l1,h2,l2,h3,l3;
            bsplit(accG[t][0],h0,l0); bsplit(accG[t][1],h1,l1);
            bsplit(accG[t][2],h2,l2); bsplit(accG[t][3],h3,l3);
            const int r1 = gm0 + g, r2 = gm0 + g + 8;
            *(__nv_bfloat162*)&sGh[r1 * P + col] = __halves2bfloat162(h0, h1);
            *(__nv_bfloat162*)&sGl[r1 * P + col] = __halves2bfloat162(l0, l1);
            *(__nv_bfloat162*)&sGh[r2 * P + col] = __halves2bfloat162(h2, h3);
            *(__nv_bfloat162*)&sGl[r2 * P + col] = __halves2bfloat162(l2, l3);
        }
    }
    __syncthreads();   // single barrier: G + H stores visible to all warps

    // ========== Phase B: T = H @ G ==========
    // n0=0 warps, kk>=2: G[0:32,32:64] is absent -> trans-read G[32:64,0:32] (symmetry).
    float accT[4][4] = {};
    {
        const unsigned a3  = sbase + OFF_HH + 2u * ((m0 + 8 * b8 + q) * P + 8 * b16);
        const unsigned b3n = sbase + OFF_GH + 2u * ((n0 + q + 8 * b16) * P + 8 * b8);
        const unsigned b3t = sbase + OFF_GH + 2u * ((32 + 8 * b8 + q) * P + 8 * b16);
        #pragma unroll
        for (int kk = 0; kk < 4; ++kk) {
            unsigned ah[4], al[4];
            ldsm_x4(ah, a3 + kk * 32);
            ldsm_x4(al, a3 + kk * 32 + PLANE_B);
            #pragma unroll
            for (int p = 0; p < 2; ++p) {
                unsigned bh[4], bl[4];
                if (n0 == 0 && kk >= 2) {
                    ldsm_x4t(bh, b3t + (kk - 2) * 16 * PB + p * 32);
                    ldsm_x4t(bl, b3t + (kk - 2) * 16 * PB + p * 32 + PLANE_B);
                } else {
                    ldsm_x4(bh, b3n + kk * 32 + p * 16 * PB);
                    ldsm_x4(bl, b3n + kk * 32 + p * 16 * PB + PLANE_B);
                }
                mma16(accT[2*p  ], ah, bh    );
                mma16(accT[2*p  ], al, bh    );
                mma16(accT[2*p  ], ah, bl    );
                mma16(accT[2*p+1], ah, bh + 2);
                mma16(accT[2*p+1], al, bh + 2);
                mma16(accT[2*p+1], ah, bl + 2);
            }
        }
    }

    // ========== Epilogue: out = F .* T + QF  (rows < 50) ==========
    float* ob = outg + (size_t)b * BTOK;
    const int r1 = m0 + g;
    const int r2 = m0 + g + 8;
    #pragma unroll
    for (int t = 0; t < 4; ++t) {
        const int col = n0 + 8 * t + 2 * t4;
        if (r1 < NTOK) {
            float2 fh = __bfloat1622float2(*(__nv_bfloat162*)&sFh[r1 * P + col]);
            float2 fl = __bfloat1622float2(*(__nv_bfloat162*)&sFl[r1 * P + col]);
            float2 o;
            o.x = (fh.x + fl.x) * accT[t][0] + accQ[t][0];
            o.y = (fh.y + fl.y) * accT[t][1] + accQ[t][1];
            *(float2*)&ob[r1 * 64 + col] = o;
        }
        if (r2 < NTOK) {
            float2 fh = __bfloat1622float2(*(__nv_bfloat162*)&sFh[r2 * P + col]);
            float2 fl = __bfloat1622float2(*(__nv_bfloat162*)&sFl[r2 * P + col]);
            float2 o;
            o.x = (fh.x + fl.x) * accT[t][2] + accQ[t][2];
            o.y = (fh.y + fl.y) * accT[t][3] + accQ[t][3];
            *(float2*)&ob[r2 * 64 + col] = o;
        }
    }
}

extern "C" void kernel_launch(void* const* d_in, const int* in_sizes, int n_in,
                              void* d_out, int out_size)
{
    const float* F  = (const float*)d_in[0];
    const float* Kw = (const float*)d_in[1];
    const float* Qw = (const float*)d_in[2];
    float* out      = (float*)d_out;

    const int B = in_sizes[0] / BTOK;                   // 8192

    cudaFuncSetAttribute(SAM3E_kernel,
                         cudaFuncAttributeMaxDynamicSharedMemorySize, SMEM_BYTES);

    SAM3E_prep<<<1, 256>>>(Kw, Qw);
    SAM3E_kernel<<<B, 256, SMEM_BYTES>>>(F, out);
}